// round 4
// baseline (speedup 1.0000x reference)
#include <cuda_runtime.h>
#include <cstdint>
#include <cstddef>

#define NN 10000
#define NE 320000
#define FIN 512
#define HH 256

// ---------------- scratch (device globals; no allocation) ----------------
__device__ float g_Xs[NN * HH];
__device__ float g_Xd[NN * HH];
__device__ float g_agg[NN * HH];
__device__ float g_deg[NN];
__device__ float g_P[NN * HH];
__device__ float g_x1h[NN * HH];
__device__ float g_x1[NN * HH];
__device__ float g_Y1[NN * HH];
__device__ float g_Y2[NN * HH];
__device__ float g_EA1[(size_t)NE * HH];

// ---------------- f32x2 helpers ----------------
__device__ __forceinline__ unsigned long long pack2(float v) {
    unsigned long long r;
    unsigned int u = __float_as_uint(v);
    asm("mov.b64 %0, {%1,%1};" : "=l"(r) : "r"(u));
    return r;
}
__device__ __forceinline__ void fma2(unsigned long long& acc, unsigned long long a, unsigned long long b) {
    asm("fma.rn.f32x2 %0, %1, %2, %0;" : "+l"(acc) : "l"(a), "l"(b));
}
__device__ __forceinline__ float2 unpack2(unsigned long long v) {
    unsigned int lo, hi;
    asm("mov.b64 {%0,%1}, %2;" : "=r"(lo), "=r"(hi) : "l"(v));
    return make_float2(__uint_as_float(lo), __uint_as_float(hi));
}

// ---------------- utility kernels ----------------
__global__ void k_zero() {
    int idx = blockIdx.x * blockDim.x + threadIdx.x;
    const int total = NN * HH + NN;
    for (; idx < total; idx += gridDim.x * blockDim.x) {
        if (idx < NN * HH) g_agg[idx] = 0.f;
        else g_deg[idx - NN * HH] = 0.f;
    }
}
__global__ void k_deg(const int* __restrict__ ei) {
    int e = blockIdx.x * 256 + threadIdx.x;
    if (e < NE) atomicAdd(&g_deg[ei[NE + e]], 1.0f);
}
__global__ void k_scale() {
    int idx = blockIdx.x * 256 + threadIdx.x;
    if (idx < NN * HH) g_agg[idx] = g_agg[idx] / fmaxf(g_deg[idx >> 8], 1.0f);
}

// ------- generic fp32 GEMM: C = act(A[M,K] @ W[K,256](ld=256) + bias + addC) -------
__global__ __launch_bounds__(256) void k_sgemm(
    const float* __restrict__ A, const float* __restrict__ W,
    const float* __restrict__ bias, const float* __restrict__ addC,
    float* __restrict__ C, int M, int K, int relu)
{
    __shared__ float As[16][64];
    __shared__ float Ws[16][64];
    int tid = threadIdx.x;
    int tx = tid & 15, ty = tid >> 4;
    int row0 = blockIdx.x * 64, col0 = blockIdx.y * 64;
    float acc[4][4] = {};
    int ar = tid >> 2, ac = (tid & 3) << 2;
    int wr = tid >> 4, wc = (tid & 15) << 2;
    for (int k0 = 0; k0 < K; k0 += 16) {
        float4 av = make_float4(0.f, 0.f, 0.f, 0.f);
        if (row0 + ar < M) av = *(const float4*)(A + (size_t)(row0 + ar) * K + k0 + ac);
        As[ac + 0][ar] = av.x; As[ac + 1][ar] = av.y;
        As[ac + 2][ar] = av.z; As[ac + 3][ar] = av.w;
        *(float4*)&Ws[wr][wc] = *(const float4*)(W + (size_t)(k0 + wr) * HH + col0 + wc);
        __syncthreads();
#pragma unroll
        for (int k = 0; k < 16; k++) {
            float a[4], w[4];
#pragma unroll
            for (int i = 0; i < 4; i++) a[i] = As[k][ty * 4 + i];
#pragma unroll
            for (int j = 0; j < 4; j++) w[j] = Ws[k][tx * 4 + j];
#pragma unroll
            for (int i = 0; i < 4; i++)
#pragma unroll
                for (int j = 0; j < 4; j++) acc[i][j] += a[i] * w[j];
        }
        __syncthreads();
    }
#pragma unroll
    for (int i = 0; i < 4; i++) {
        int r = row0 + ty * 4 + i;
        if (r >= M) continue;
#pragma unroll
        for (int j = 0; j < 4; j++) {
            int c = col0 + tx * 4 + j;
            float v = acc[i][j];
            if (bias) v += bias[c];
            if (addC) v += addC[(size_t)r * HH + c];
            if (relu) v = fmaxf(v, 0.f);
            C[(size_t)r * HH + c] = v;
        }
    }
}

// ---------------- fused edge layer 0 ----------------
// EA1[e] = relu(Xs[src]+Xd[dst]+ea@W3+be0a) @ We0b + be0b ; agg[dst] += EA1[e]
__global__ __launch_bounds__(256) void k_edge_gemm0(
    const int* __restrict__ ei, const float* __restrict__ eattr,
    const float* __restrict__ We0a, const float* __restrict__ be0a,
    const float* __restrict__ We0b, const float* __restrict__ be0b)
{
    __shared__ float As[8][64];
    __shared__ float Ws[8 * 256];
    __shared__ float w3f[256 * 6];
    __shared__ float b0s[256];
    __shared__ float ea_s[64][6];
    __shared__ int src_s[64], dst_s[64];

    int tid = threadIdx.x;
    int e0 = blockIdx.x * 64;
    if (tid < 64) { src_s[tid] = ei[e0 + tid]; dst_s[tid] = ei[NE + e0 + tid]; }
    b0s[tid] = be0a[tid];
    for (int idx = tid; idx < 1536; idx += 256) {
        int j = idx >> 8, k = idx & 255;
        w3f[k * 6 + j] = We0a[(size_t)(1024 + j) * HH + k];
    }
    for (int idx = tid; idx < 384; idx += 256)
        ea_s[idx / 6][idx % 6] = eattr[(size_t)(e0 + idx / 6) * 6 + (idx % 6)];
    __syncthreads();

    int ty = tid >> 5, tx = tid & 31;
    int am = tid >> 2, ak = (tid & 3) << 1;
    int wr = tid >> 5, wc = (tid & 31) << 2;
    const float* xs_row = g_Xs + (size_t)src_s[am] * HH;
    const float* xd_row = g_Xd + (size_t)dst_s[am] * HH;
    float ear[6];
#pragma unroll
    for (int j = 0; j < 6; j++) ear[j] = ea_s[am][j];

    unsigned long long acc[8][4];
#pragma unroll
    for (int i = 0; i < 8; i++)
#pragma unroll
        for (int jp = 0; jp < 4; jp++) acc[i][jp] = 0ull;

    // prefetch chunk 0
    float2 xs = *(const float2*)(xs_row + ak);
    float2 xd = *(const float2*)(xd_row + ak);
    float4 wp0 = *(const float4*)(We0b + (size_t)wr * HH + wc);
    float4 wp1 = *(const float4*)(We0b + (size_t)wr * HH + wc + 128);

    for (int k0 = 0; k0 < 256; k0 += 8) {
        int kg = k0 + ak;
        float v0 = xs.x + xd.x + b0s[kg];
        float v1 = xs.y + xd.y + b0s[kg + 1];
#pragma unroll
        for (int j = 0; j < 6; j++) {
            v0 += ear[j] * w3f[kg * 6 + j];
            v1 += ear[j] * w3f[(kg + 1) * 6 + j];
        }
        As[ak][am]     = fmaxf(v0, 0.f);
        As[ak + 1][am] = fmaxf(v1, 0.f);
        *(float4*)(Ws + wr * 256 + wc)       = wp0;
        *(float4*)(Ws + wr * 256 + wc + 128) = wp1;
        __syncthreads();
        if (k0 + 8 < 256) {
            xs = *(const float2*)(xs_row + kg + 8);
            xd = *(const float2*)(xd_row + kg + 8);
            wp0 = *(const float4*)(We0b + (size_t)(k0 + 8 + wr) * HH + wc);
            wp1 = *(const float4*)(We0b + (size_t)(k0 + 8 + wr) * HH + wc + 128);
        }
#pragma unroll
        for (int k = 0; k < 8; k++) {
            unsigned long long w2[4];
#pragma unroll
            for (int jp = 0; jp < 4; jp++)
                w2[jp] = *(const unsigned long long*)(Ws + k * 256 + (tx << 1) + (jp << 6));
#pragma unroll
            for (int i = 0; i < 8; i++) {
                unsigned long long a2 = pack2(As[k][ty * 8 + i]);
#pragma unroll
                for (int jp = 0; jp < 4; jp++) fma2(acc[i][jp], a2, w2[jp]);
            }
        }
        __syncthreads();
    }
#pragma unroll
    for (int i = 0; i < 8; i++) {
        int m = ty * 8 + i;
        size_t rbase = (size_t)(e0 + m) * HH;
        int d = dst_s[m];
#pragma unroll
        for (int jp = 0; jp < 4; jp++) {
            int c = (tx << 1) + (jp << 6);
            float2 v = unpack2(acc[i][jp]);
            v.x += be0b[c];
            v.y += be0b[c + 1];
            *(float2*)(g_EA1 + rbase + c) = v;
            atomicAdd(&g_agg[(size_t)d * HH + c], v.x);
            atomicAdd(&g_agg[(size_t)d * HH + c + 1], v.y);
        }
    }
}

// ----- chain2 tile GEMM: acc += Asm[64x256] @ Wg[256x256], W staged via smem -----
__device__ __forceinline__ void tile_gemm(const float* __restrict__ Asm, const float* __restrict__ Wg,
                                          float* __restrict__ Wsm, unsigned long long (&acc)[8][4],
                                          int tid, int ty, int tx)
{
    int wr = tid >> 5, wc = (tid & 31) << 2;
    float4 wp0 = *(const float4*)(Wg + (size_t)wr * HH + wc);
    float4 wp1 = *(const float4*)(Wg + (size_t)wr * HH + wc + 128);
    for (int k0 = 0; k0 < 256; k0 += 8) {
        *(float4*)(Wsm + wr * 256 + wc)       = wp0;
        *(float4*)(Wsm + wr * 256 + wc + 128) = wp1;
        __syncthreads();
        if (k0 + 8 < 256) {
            wp0 = *(const float4*)(Wg + (size_t)(k0 + 8 + wr) * HH + wc);
            wp1 = *(const float4*)(Wg + (size_t)(k0 + 8 + wr) * HH + wc + 128);
        }
#pragma unroll
        for (int k = 0; k < 8; k++) {
            unsigned long long w2[4];
#pragma unroll
            for (int jp = 0; jp < 4; jp++)
                w2[jp] = *(const unsigned long long*)(Wsm + k * 256 + (tx << 1) + (jp << 6));
#pragma unroll
            for (int i = 0; i < 8; i++) {
                unsigned long long a2 = pack2(Asm[(ty * 8 + i) * 256 + k0 + k]);
#pragma unroll
                for (int jp = 0; jp < 4; jp++) fma2(acc[i][jp], a2, w2[jp]);
            }
        }
        __syncthreads();
    }
}

// ---------------- fused edge layer 1 + predictor ----------------
__global__ __launch_bounds__(256, 1) void k_chain2(
    const int* __restrict__ ei,
    const float* __restrict__ We1a, const float* __restrict__ be1a,
    const float* __restrict__ We1b, const float* __restrict__ be1b,
    const float* __restrict__ Wp1,  const float* __restrict__ bp1,
    const float* __restrict__ Wp2,  const float* __restrict__ bp2,
    float* __restrict__ out)
{
    extern __shared__ float sm[];
    float* A_sm = sm;                 // 64*256 : EA1, later EA2
    float* B_sm = sm + 64 * 256;      // 64*256 : h1
    float* W_sm = sm + 2 * 64 * 256;  // 8*256
    __shared__ int src_s[64], dst_s[64];
    __shared__ float wp2s[256];

    int tid = threadIdx.x;
    int e0 = blockIdx.x * 64;
    if (tid < 64) { src_s[tid] = ei[e0 + tid]; dst_s[tid] = ei[NE + e0 + tid]; }
    wp2s[tid] = Wp2[tid];
#pragma unroll
    for (int it = 0; it < 16; it++) {
        int lin = it * 256 + tid;
        int r = lin >> 6, c4 = (lin & 63) << 2;
        *(float4*)(A_sm + r * 256 + c4) = *(const float4*)(g_EA1 + (size_t)(e0 + r) * HH + c4);
    }
    __syncthreads();

    int ty = tid >> 5, tx = tid & 31;
    unsigned long long acc[8][4];

    // GEMM1: h1 = relu(EA1 @ We1a[512:768] + Y1[src] + Y2[dst] + be1a)
#pragma unroll
    for (int i = 0; i < 8; i++)
#pragma unroll
        for (int jp = 0; jp < 4; jp++) acc[i][jp] = 0ull;
    tile_gemm(A_sm, We1a + 512 * HH, W_sm, acc, tid, ty, tx);
#pragma unroll
    for (int i = 0; i < 8; i++) {
        int m = ty * 8 + i;
        const float* y1r = g_Y1 + (size_t)src_s[m] * HH;
        const float* y2r = g_Y2 + (size_t)dst_s[m] * HH;
#pragma unroll
        for (int jp = 0; jp < 4; jp++) {
            int c = (tx << 1) + (jp << 6);
            float2 v = unpack2(acc[i][jp]);
            v.x += be1a[c]     + y1r[c]     + y2r[c];
            v.y += be1a[c + 1] + y1r[c + 1] + y2r[c + 1];
            B_sm[m * 256 + c]     = fmaxf(v.x, 0.f);
            B_sm[m * 256 + c + 1] = fmaxf(v.y, 0.f);
        }
    }
    __syncthreads();

    // GEMM2: EA2 = h1 @ We1b + be1b + EA1  (in-place into A_sm)
#pragma unroll
    for (int i = 0; i < 8; i++)
#pragma unroll
        for (int jp = 0; jp < 4; jp++) acc[i][jp] = 0ull;
    tile_gemm(B_sm, We1b, W_sm, acc, tid, ty, tx);
#pragma unroll
    for (int i = 0; i < 8; i++) {
        int m = ty * 8 + i;
#pragma unroll
        for (int jp = 0; jp < 4; jp++) {
            int c = (tx << 1) + (jp << 6);
            float2 v = unpack2(acc[i][jp]);
            A_sm[m * 256 + c]     = v.x + be1b[c]     + A_sm[m * 256 + c];
            A_sm[m * 256 + c + 1] = v.y + be1b[c + 1] + A_sm[m * 256 + c + 1];
        }
    }
    __syncthreads();

    // GEMM3: h = leaky_relu(EA2 @ Wp1 + bp1); out = h . wp2 + bp2
#pragma unroll
    for (int i = 0; i < 8; i++)
#pragma unroll
        for (int jp = 0; jp < 4; jp++) acc[i][jp] = 0ull;
    tile_gemm(A_sm, Wp1, W_sm, acc, tid, ty, tx);
#pragma unroll
    for (int i = 0; i < 8; i++) {
        float p = 0.f;
#pragma unroll
        for (int jp = 0; jp < 4; jp++) {
            int c = (tx << 1) + (jp << 6);
            float2 v = unpack2(acc[i][jp]);
            float h0v = v.x + bp1[c];
            h0v = (h0v > 0.f) ? h0v : 0.01f * h0v;
            p += h0v * wp2s[c];
            float h1v = v.y + bp1[c + 1];
            h1v = (h1v > 0.f) ? h1v : 0.01f * h1v;
            p += h1v * wp2s[c + 1];
        }
#pragma unroll
        for (int off = 16; off > 0; off >>= 1) p += __shfl_xor_sync(0xffffffffu, p, off);
        if (tx == 0) out[e0 + ty * 8 + i] = p + bp2[0];
    }
}

// ---------------- host launcher ----------------
extern "C" void kernel_launch(void* const* d_in, const int* in_sizes, int n_in,
                              void* d_out, int out_size)
{
    (void)in_sizes; (void)n_in; (void)out_size;
    const float* x    = (const float*)d_in[0];
    const int*   ei   = (const int*)  d_in[1];
    const float* ea   = (const float*)d_in[2];
    const float* We0a = (const float*)d_in[3];
    const float* be0a = (const float*)d_in[4];
    const float* We0b = (const float*)d_in[5];
    const float* be0b = (const float*)d_in[6];
    const float* Wn0a = (const float*)d_in[7];
    const float* bn0a = (const float*)d_in[8];
    const float* Wn0b = (const float*)d_in[9];
    const float* bn0b = (const float*)d_in[10];
    const float* We1a = (const float*)d_in[11];
    const float* be1a = (const float*)d_in[12];
    const float* We1b = (const float*)d_in[13];
    const float* be1b = (const float*)d_in[14];
    // d_in[15..18] = Wn1a,bn1a,Wn1b,bn1b : dead code (x2 never reaches the output)
    const float* Wp1  = (const float*)d_in[19];
    const float* bp1  = (const float*)d_in[20];
    const float* Wp2  = (const float*)d_in[21];
    const float* bp2  = (const float*)d_in[22];
    float* out = (float*)d_out;

    cudaFuncSetAttribute(k_chain2, cudaFuncAttributeMaxDynamicSharedMemorySize, 139264);

    void *p_Xs, *p_Xd, *p_agg, *p_P, *p_x1h, *p_x1, *p_Y1, *p_Y2;
    cudaGetSymbolAddress(&p_Xs,  g_Xs);
    cudaGetSymbolAddress(&p_Xd,  g_Xd);
    cudaGetSymbolAddress(&p_agg, g_agg);
    cudaGetSymbolAddress(&p_P,   g_P);
    cudaGetSymbolAddress(&p_x1h, g_x1h);
    cudaGetSymbolAddress(&p_x1,  g_x1);
    cudaGetSymbolAddress(&p_Y1,  g_Y1);
    cudaGetSymbolAddress(&p_Y2,  g_Y2);

    dim3 gN((NN + 63) / 64, 4);

    k_zero<<<2048, 256>>>();
    k_deg<<<NE / 256, 256>>>(ei);

    // layer-0 edge precompute: Xs = x@We0a[0:512], Xd = x@We0a[512:1024]
    k_sgemm<<<gN, 256>>>(x, We0a,            nullptr, nullptr, (float*)p_Xs, NN, FIN, 0);
    k_sgemm<<<gN, 256>>>(x, We0a + 512 * HH, nullptr, nullptr, (float*)p_Xd, NN, FIN, 0);

    // fused edge layer 0 -> EA1, agg(+=)
    k_edge_gemm0<<<NE / 64, 256>>>(ei, ea, We0a, be0a, We0b, be0b);
    k_scale<<<(NN * HH + 255) / 256, 256>>>();

    // node MLP 0: x1 = relu(x@Wn0a_top + agg@Wn0a_bot + bn0a) @ Wn0b + bn0b
    k_sgemm<<<gN, 256>>>(x, Wn0a, nullptr, nullptr, (float*)p_P, NN, FIN, 0);
    k_sgemm<<<gN, 256>>>((const float*)p_agg, Wn0a + 512 * HH, bn0a, (const float*)p_P,
                         (float*)p_x1h, NN, HH, 1);
    k_sgemm<<<gN, 256>>>((const float*)p_x1h, Wn0b, bn0b, nullptr, (float*)p_x1, NN, HH, 0);

    // layer-1 edge precompute: Y1 = x1@We1a[0:256], Y2 = x1@We1a[256:512]
    k_sgemm<<<gN, 256>>>((const float*)p_x1, We1a,            nullptr, nullptr, (float*)p_Y1, NN, HH, 0);
    k_sgemm<<<gN, 256>>>((const float*)p_x1, We1a + 256 * HH, nullptr, nullptr, (float*)p_Y2, NN, HH, 0);

    // fused edge layer 1 + residual + predictor
    k_chain2<<<NE / 64, 256, 139264>>>(ei, We1a, be1a, We1b, be1b, Wp1, bp1, Wp2, bp2, out);
}